// round 5
// baseline (speedup 1.0000x reference)
#include <cuda_runtime.h>

// CrossCompress: B=16384 rows, D=128.
// item_out   = v*(e.w_vv) + e*(v.w_ev) + bias_v
// entity_out = v*(e.w_ve) + e*(v.w_ee) + bias_e
//
// R5: 2 rows/warp (MLP=4), 256-thread blocks, regs<=51 -> 40 warps/SM.
// Reduction uses quad-transpose trick: 30 shuffles per warp instead of 40,
// with shorter dependency chains.

#define B_ROWS 16384
#define D_DIM  128
#define RPW    2

__global__ __launch_bounds__(256, 5)
void crosscompress_kernel(const float4* __restrict__ v_in,
                          const float4* __restrict__ e_in,
                          const float4* __restrict__ w_vv,
                          const float4* __restrict__ w_ve,
                          const float4* __restrict__ w_ev,
                          const float4* __restrict__ w_ee,
                          const float4* __restrict__ bias_v,
                          const float4* __restrict__ bias_e,
                          float4* __restrict__ out_item,
                          float4* __restrict__ out_ent)
{
    const int gtid = blockIdx.x * blockDim.x + threadIdx.x;
    const int warp = gtid >> 5;
    const int lane = gtid & 31;
    const int row0 = warp * RPW;

    const int idx0 = row0 * 32 + lane;
    const int idx1 = idx0 + 32;

    // Row data: 4 independent LDG.128
    const float4 v0 = v_in[idx0];
    const float4 e0 = e_in[idx0];
    const float4 v1 = v_in[idx1];
    const float4 e1 = e_in[idx1];

    // Weights (L1-resident)
    const float4 wvv = __ldg(&w_vv[lane]);
    const float4 wev = __ldg(&w_ev[lane]);
    const float4 wve = __ldg(&w_ve[lane]);
    const float4 wee = __ldg(&w_ee[lane]);

    // 8 per-lane partial dots. kind: 0=vv(e.wvv) 1=ev(v.wev) 2=ve(e.wve) 3=ee(v.wee)
    float d0 = e0.x*wvv.x + e0.y*wvv.y + e0.z*wvv.z + e0.w*wvv.w;
    float d1 = v0.x*wev.x + v0.y*wev.y + v0.z*wev.z + v0.w*wev.w;
    float d2 = e0.x*wve.x + e0.y*wve.y + e0.z*wve.z + e0.w*wve.w;
    float d3 = v0.x*wee.x + v0.y*wee.y + v0.z*wee.z + v0.w*wee.w;
    float d4 = e1.x*wvv.x + e1.y*wvv.y + e1.z*wvv.z + e1.w*wvv.w;
    float d5 = v1.x*wev.x + v1.y*wev.y + v1.z*wev.z + v1.w*wev.w;
    float d6 = e1.x*wve.x + e1.y*wve.y + e1.z*wve.z + e1.w*wve.w;
    float d7 = v1.x*wee.x + v1.y*wee.y + v1.z*wee.z + v1.w*wee.w;

    // Level 1+2: butterfly within quads on all 8 values (16 SHFL)
    #pragma unroll
    for (int off = 1; off <= 2; off <<= 1) {
        d0 += __shfl_xor_sync(0xFFFFFFFFu, d0, off);
        d1 += __shfl_xor_sync(0xFFFFFFFFu, d1, off);
        d2 += __shfl_xor_sync(0xFFFFFFFFu, d2, off);
        d3 += __shfl_xor_sync(0xFFFFFFFFu, d3, off);
        d4 += __shfl_xor_sync(0xFFFFFFFFu, d4, off);
        d5 += __shfl_xor_sync(0xFFFFFFFFu, d5, off);
        d6 += __shfl_xor_sync(0xFFFFFFFFu, d6, off);
        d7 += __shfl_xor_sync(0xFFFFFFFFu, d7, off);
    }

    // Transpose: lane with (lane&3)==k carries kind k for both rows
    const int k = lane & 3;
    float a0 = (k == 0) ? d0 : (k == 1) ? d1 : (k == 2) ? d2 : d3; // row0, kind k
    float a1 = (k == 0) ? d4 : (k == 1) ? d5 : (k == 2) ? d6 : d7; // row1, kind k

    // Level 4,8,16: butterfly across quads on 2 values (6 SHFL).
    // Every lane ends with the full sum for its kind (lane&3).
    #pragma unroll
    for (int off = 4; off <= 16; off <<= 1) {
        a0 += __shfl_xor_sync(0xFFFFFFFFu, a0, off);
        a1 += __shfl_xor_sync(0xFFFFFFFFu, a1, off);
    }

    // Broadcast within quads (width=4): every lane gets all 4 kinds (8 SHFL)
    const float svv0 = __shfl_sync(0xFFFFFFFFu, a0, 0, 4);
    const float sev0 = __shfl_sync(0xFFFFFFFFu, a0, 1, 4);
    const float sve0 = __shfl_sync(0xFFFFFFFFu, a0, 2, 4);
    const float see0 = __shfl_sync(0xFFFFFFFFu, a0, 3, 4);
    const float svv1 = __shfl_sync(0xFFFFFFFFu, a1, 0, 4);
    const float sev1 = __shfl_sync(0xFFFFFFFFu, a1, 1, 4);
    const float sve1 = __shfl_sync(0xFFFFFFFFu, a1, 2, 4);
    const float see1 = __shfl_sync(0xFFFFFFFFu, a1, 3, 4);

    const float4 bv = __ldg(&bias_v[lane]);
    const float4 be = __ldg(&bias_e[lane]);

    float4 oi, oe;
    oi.x = v0.x*svv0 + e0.x*sev0 + bv.x;
    oi.y = v0.y*svv0 + e0.y*sev0 + bv.y;
    oi.z = v0.z*svv0 + e0.z*sev0 + bv.z;
    oi.w = v0.w*svv0 + e0.w*sev0 + bv.w;
    oe.x = v0.x*sve0 + e0.x*see0 + be.x;
    oe.y = v0.y*sve0 + e0.y*see0 + be.y;
    oe.z = v0.z*sve0 + e0.z*see0 + be.z;
    oe.w = v0.w*sve0 + e0.w*see0 + be.w;
    out_item[idx0] = oi;
    out_ent[idx0]  = oe;

    oi.x = v1.x*svv1 + e1.x*sev1 + bv.x;
    oi.y = v1.y*svv1 + e1.y*sev1 + bv.y;
    oi.z = v1.z*svv1 + e1.z*sev1 + bv.z;
    oi.w = v1.w*svv1 + e1.w*sev1 + bv.w;
    oe.x = v1.x*sve1 + e1.x*see1 + be.x;
    oe.y = v1.y*sve1 + e1.y*see1 + be.y;
    oe.z = v1.z*sve1 + e1.z*see1 + be.z;
    oe.w = v1.w*sve1 + e1.w*see1 + be.w;
    out_item[idx1] = oi;
    out_ent[idx1]  = oe;
}

extern "C" void kernel_launch(void* const* d_in, const int* in_sizes, int n_in,
                              void* d_out, int out_size)
{
    const float4* v_in   = (const float4*)d_in[0];
    const float4* e_in   = (const float4*)d_in[1];
    const float4* w_vv   = (const float4*)d_in[2];
    const float4* w_ve   = (const float4*)d_in[3];
    const float4* w_ev   = (const float4*)d_in[4];
    const float4* w_ee   = (const float4*)d_in[5];
    const float4* bias_v = (const float4*)d_in[6];
    const float4* bias_e = (const float4*)d_in[7];

    float* out = (float*)d_out;
    float4* out_item = (float4*)out;
    float4* out_ent  = (float4*)(out + B_ROWS * D_DIM);

    // 8 warps/block, 2 rows/warp -> 16 rows/block -> 1024 blocks
    const int threads = 256;
    const int blocks  = B_ROWS / (8 * RPW);   // 1024

    crosscompress_kernel<<<blocks, threads>>>(v_in, e_in, w_vv, w_ve, w_ev, w_ee,
                                              bias_v, bias_e, out_item, out_ent);
}

// round 6
// speedup vs baseline: 1.0257x; 1.0257x over previous
#include <cuda_runtime.h>

// CrossCompress: B=16384 rows, D=128.
// item_out   = v*(e.w_vv) + e*(v.w_ev) + bias_v
// entity_out = v*(e.w_ve) + e*(v.w_ee) + bias_e
//
// R6: R3 geometry (4 rows/warp, 128-thr blocks, grid 1024) restructured as a
// depth-1 software pipeline: while row r runs its shuffle-reduce/combine,
// row r+1's two LDG.128s are already in flight, and row r's stores issue
// immediately. This keeps the LTS/L1 path continuously busy instead of the
// load-burst / mem-idle-reduce / store-burst phase pattern.

#define B_ROWS 16384
#define D_DIM  128
#define RPW    4

__global__ __launch_bounds__(128)
void crosscompress_kernel(const float4* __restrict__ v_in,
                          const float4* __restrict__ e_in,
                          const float4* __restrict__ w_vv,
                          const float4* __restrict__ w_ve,
                          const float4* __restrict__ w_ev,
                          const float4* __restrict__ w_ee,
                          const float4* __restrict__ bias_v,
                          const float4* __restrict__ bias_e,
                          float4* __restrict__ out_item,
                          float4* __restrict__ out_ent)
{
    const int gtid = blockIdx.x * blockDim.x + threadIdx.x;
    const int warp = gtid >> 5;
    const int lane = gtid & 31;
    const int idx0 = (warp * RPW) * 32 + lane;

    // Weights + biases: L1-resident after first touch
    const float4 wvv = __ldg(&w_vv[lane]);
    const float4 wev = __ldg(&w_ev[lane]);
    const float4 wve = __ldg(&w_ve[lane]);
    const float4 wee = __ldg(&w_ee[lane]);
    const float4 bv  = __ldg(&bias_v[lane]);
    const float4 be  = __ldg(&bias_e[lane]);

    // Prime the pipeline: row 0 loads
    float4 v_cur = v_in[idx0];
    float4 e_cur = e_in[idx0];

    #pragma unroll
    for (int r = 0; r < RPW; r++) {
        const int idx = idx0 + r * 32;

        // Prefetch next row while this row reduces
        float4 v_nxt, e_nxt;
        if (r < RPW - 1) {
            v_nxt = v_in[idx + 32];
            e_nxt = e_in[idx + 32];
        }

        // Per-lane partial dots for current row
        float d_vv = e_cur.x*wvv.x + e_cur.y*wvv.y + e_cur.z*wvv.z + e_cur.w*wvv.w;
        float d_ev = v_cur.x*wev.x + v_cur.y*wev.y + v_cur.z*wev.z + v_cur.w*wev.w;
        float d_ve = e_cur.x*wve.x + e_cur.y*wve.y + e_cur.z*wve.z + e_cur.w*wve.w;
        float d_ee = v_cur.x*wee.x + v_cur.y*wee.y + v_cur.z*wee.z + v_cur.w*wee.w;

        // Butterfly reduce (4 parallel chains, 20 SHFL)
        #pragma unroll
        for (int off = 16; off > 0; off >>= 1) {
            d_vv += __shfl_xor_sync(0xFFFFFFFFu, d_vv, off);
            d_ev += __shfl_xor_sync(0xFFFFFFFFu, d_ev, off);
            d_ve += __shfl_xor_sync(0xFFFFFFFFu, d_ve, off);
            d_ee += __shfl_xor_sync(0xFFFFFFFFu, d_ee, off);
        }

        // Combine + store immediately (spreads store traffic)
        float4 oi, oe;
        oi.x = v_cur.x*d_vv + e_cur.x*d_ev + bv.x;
        oi.y = v_cur.y*d_vv + e_cur.y*d_ev + bv.y;
        oi.z = v_cur.z*d_vv + e_cur.z*d_ev + bv.z;
        oi.w = v_cur.w*d_vv + e_cur.w*d_ev + bv.w;
        oe.x = v_cur.x*d_ve + e_cur.x*d_ee + be.x;
        oe.y = v_cur.y*d_ve + e_cur.y*d_ee + be.y;
        oe.z = v_cur.z*d_ve + e_cur.z*d_ee + be.z;
        oe.w = v_cur.w*d_ve + e_cur.w*d_ee + be.w;
        out_item[idx] = oi;
        out_ent[idx]  = oe;

        v_cur = v_nxt;
        e_cur = e_nxt;
    }
}

extern "C" void kernel_launch(void* const* d_in, const int* in_sizes, int n_in,
                              void* d_out, int out_size)
{
    const float4* v_in   = (const float4*)d_in[0];
    const float4* e_in   = (const float4*)d_in[1];
    const float4* w_vv   = (const float4*)d_in[2];
    const float4* w_ve   = (const float4*)d_in[3];
    const float4* w_ev   = (const float4*)d_in[4];
    const float4* w_ee   = (const float4*)d_in[5];
    const float4* bias_v = (const float4*)d_in[6];
    const float4* bias_e = (const float4*)d_in[7];

    float* out = (float*)d_out;
    float4* out_item = (float4*)out;
    float4* out_ent  = (float4*)(out + B_ROWS * D_DIM);

    // 4 warps/block, 4 rows/warp -> 16 rows/block -> 1024 blocks
    const int threads = 128;
    const int blocks  = B_ROWS / (4 * RPW);   // 1024

    crosscompress_kernel<<<blocks, threads>>>(v_in, e_in, w_vv, w_ve, w_ev, w_ee,
                                              bias_v, bias_e, out_item, out_ent);
}